// round 16
// baseline (speedup 1.0000x reference)
#include <cuda_runtime.h>
#include <cuda_bf16.h>
#include <math.h>

#define NPTS   64              // interpolation intervals over s in [0, 10]
#define TAB_N  (NPTS + 4)      // 68: +1 guard below, +2 above (Catmull-Rom)
#define S_MAX  10.0f           // 1/sqrt(EPS2)
#define EPS2   0.01f
#define BLK    128             // threads per block
#define SPB    128             // samples per tile
#define TPB    4               // tiles per block (pipelined)
#define STAGES 3               // ring depth
#define TILE_BYTES (SPB * 18 * 4)   // 9216 B

// g(s) = d(MLP)/ds at s_k = (k-1)*h, k = 0..NPTS+3
__device__ float g_table[TAB_N];
__device__ float minv_g[3];
__device__ unsigned g_done = 0;   // builder completion count (reset each launch)
__device__ unsigned g_fin  = 0;   // block completion count   (reset each launch)

__device__ __forceinline__ unsigned smem_u32(const void* p) {
    unsigned a;
    asm("{ .reg .u64 t; cvta.to.shared.u64 t, %1; cvt.u32.u64 %0, t; }"
        : "=r"(a) : "l"(p));
    return a;
}

__device__ __forceinline__ void mbar_wait(unsigned mbar, unsigned parity) {
    asm volatile(
        "{\n\t.reg .pred P;\n\t"
        "W%=:\n\t"
        "mbarrier.try_wait.parity.shared.b64 P, [%0], %1;\n\t"
        "@P bra D%=;\n\t"
        "bra W%=;\n\t"
        "D%=:\n\t}"
        :: "r"(mbar), "r"(parity) : "memory");
}

// Catmull-Rom lookup of g(s) from a shared-memory table
__device__ __forceinline__ float lookup_g(const float* __restrict__ tab, float s)
{
    const float inv_h = (float)NPTS / S_MAX;
    const float u = s * inv_h;
    int i = (int)u;
    if (i > NPTS - 1) i = NPTS - 1;
    const float t  = u - (float)i;
    const float p0 = tab[i];
    const float p1 = tab[i + 1];
    const float p2 = tab[i + 2];
    const float p3 = tab[i + 3];
    return p1 + 0.5f * t * ((p2 - p0)
           + t * ((2.0f * p0 - 5.0f * p1 + 4.0f * p2 - p3)
           + t * (3.0f * (p1 - p2) + (p3 - p0))));
}

__device__ __forceinline__ void sample_row(float* __restrict__ r,
                                           const float* __restrict__ tab,
                                           float mi0, float mi1, float mi2)
{
    float q[9], p[9], f[9];
    #pragma unroll
    for (int c = 0; c < 9; c++) { q[c] = r[c]; p[c] = r[9 + c]; }
    #pragma unroll
    for (int c = 0; c < 3; c++) {
        r[c]     = p[c]     * mi0;          // dq/dt
        r[3 + c] = p[3 + c] * mi1;
        r[6 + c] = p[6 + c] * mi2;
    }
    #pragma unroll
    for (int c = 0; c < 9; c++) f[c] = 0.0f;
    const int PI[3] = {0, 0, 1};
    const int PJ[3] = {1, 2, 2};
    #pragma unroll
    for (int pr = 0; pr < 3; pr++) {
        const int bi = PI[pr] * 3, bj = PJ[pr] * 3;
        const float dx = q[bi]     - q[bj];
        const float dy = q[bi + 1] - q[bj + 1];
        const float dz = q[bi + 2] - q[bj + 2];
        const float r2 = fmaf(dx, dx, fmaf(dy, dy, fmaf(dz, dz, EPS2)));
        const float s  = rsqrtf(r2);            // 1/d
        const float g  = lookup_g(tab, s);      // dV_pair/ds
        const float w  = g * s * s * s;         // g / d^3
        f[bi]     += w * dx;  f[bi + 1] += w * dy;  f[bi + 2] += w * dz;
        f[bj]     -= w * dx;  f[bj + 1] -= w * dy;  f[bj + 2] -= w * dz;
    }
    #pragma unroll
    for (int c = 0; c < 9; c++) r[9 + c] = f[c];    // dp/dt
}

// ---------------------------------------------------------------------------
// Single fused kernel. Blocks 0..TAB_N-1 first build one table point each
// (row-dot straight from global W2; h1/u shared via 1 KB smem), publish with
// st.global.cg + red.release.gpu. ALL blocks issue ring-prologue bulk loads
// before the build/wait so the ~1us build overlaps the input prefetch.
// Wait = ld.acquire.gpu spin + fixed nanosleep(64): no L1 flush, no backoff.
// Then everyone runs the R15 3-stage bulk-copy ring over TPB tiles.
// ---------------------------------------------------------------------------
__global__ void __launch_bounds__(BLK) hnn_fused(
    const float* __restrict__ z,  const float* __restrict__ log_m,
    const float* __restrict__ W1, const float* __restrict__ b1,
    const float* __restrict__ W2, const float* __restrict__ b2,
    const float* __restrict__ W3,
    float* __restrict__ out, int B)
{
    __shared__ __align__(16) float sbuf[STAGES][SPB * 18];  // 27648 B
    __shared__ __align__(16) float s_tab[TAB_N];
    __shared__ __align__(8)  unsigned long long mbar[STAGES];
    __shared__ float sh1b[128], sub[128], red[4];
    __shared__ float s_minv[3];

    const int tid   = threadIdx.x;
    const int bid   = blockIdx.x;
    const int ntf   = B / SPB;                    // full tiles
    const int tile0 = bid * TPB;
    const int nt    = max(0, min(TPB, ntf - tile0));
    const unsigned mb0 = smem_u32(mbar);

    // ---- ring prologue: mbar init + first bulk loads (overlap the build) ----
    if (tid == 0 && nt > 0) {
        #pragma unroll
        for (int s = 0; s < STAGES; s++)
            asm volatile("mbarrier.init.shared.b64 [%0], 1;"
                         :: "r"(mb0 + 8u * s) : "memory");
        asm volatile("fence.proxy.async.shared::cta;" ::: "memory");
        const int npro = min(STAGES - 1, nt);
        for (int k = 0; k < npro; k++) {
            asm volatile("mbarrier.arrive.expect_tx.shared.b64 _, [%0], %1;"
                         :: "r"(mb0 + 8u * k), "r"((unsigned)TILE_BYTES) : "memory");
            asm volatile(
                "cp.async.bulk.shared::cta.global.mbarrier::complete_tx::bytes "
                "[%0], [%1], %2, [%3];"
                :: "r"(smem_u32(sbuf[k])),
                   "l"(z + (size_t)(tile0 + k) * (SPB * 18)),
                   "r"((unsigned)TILE_BYTES), "r"(mb0 + 8u * k)
                : "memory");
        }
    }

    // ---- builder role: blocks 0..TAB_N-1 compute one table point each ----
    if (bid < TAB_N) {
        const float hstep = S_MAX / (float)NPTS;
        const float s = (float)(bid - 1) * hstep;
        {   // layer 1: h1[tid], u[tid]  (shared so every thread sees all j)
            const float w  = __ldg(&W1[tid]);
            const float a  = fmaf(w, s, __ldg(&b1[tid]));
            const float sg = 1.0f / (1.0f + __expf(-a));
            sh1b[tid] = a * sg;
            sub[tid]  = w * sg * (1.0f + a * (1.0f - sg));
        }
        __syncthreads();

        // row-k dot products straight from global W2 (one-time cost)
        float acch = __ldg(&b2[tid]), accu = 0.0f;
        const float4* wr = (const float4*)(W2 + tid * 128);
        #pragma unroll
        for (int j4 = 0; j4 < 32; j4++) {
            const float4 v = __ldg(wr + j4);
            const int j = j4 * 4;
            acch = fmaf(v.x, sh1b[j],     acch);  accu = fmaf(v.x, sub[j],     accu);
            acch = fmaf(v.y, sh1b[j + 1], acch);  accu = fmaf(v.y, sub[j + 1], accu);
            acch = fmaf(v.z, sh1b[j + 2], acch);  accu = fmaf(v.z, sub[j + 2], accu);
            acch = fmaf(v.w, sh1b[j + 3], acch);  accu = fmaf(v.w, sub[j + 3], accu);
        }
        const float sg  = 1.0f / (1.0f + __expf(-acch));
        float val = __ldg(&W3[tid]) * sg * (1.0f + acch * (1.0f - sg)) * accu;

        #pragma unroll
        for (int off = 16; off; off >>= 1)
            val += __shfl_xor_sync(0xffffffffu, val, off);
        if ((tid & 31) == 0) red[tid >> 5] = val;

        if (bid == 0 && tid < 3) {   // masses: published with the same release
            const float mv = 1.0f / (expf(__ldg(&log_m[tid])) + 1e-8f);
            asm volatile("st.global.cg.f32 [%0], %1;"
                         :: "l"(&minv_g[tid]), "f"(mv) : "memory");
        }
        __syncthreads();

        if (tid == 0) {
            const float tot = red[0] + red[1] + red[2] + red[3];
            asm volatile("st.global.cg.f32 [%0], %1;"
                         :: "l"(&g_table[bid]), "f"(tot) : "memory");
            // release: table + minv stores ordered before the count increment
            asm volatile("red.release.gpu.global.add.u32 [%0], 1;"
                         :: "l"(&g_done) : "memory");
        }
    }

    // ---- acquire the table (leader spins; fixed tiny sleep, no L1 flush) ----
    if (tid == 0) {
        unsigned c;
        while (true) {
            asm volatile("ld.acquire.gpu.global.u32 %0, [%1];"
                         : "=r"(c) : "l"(&g_done) : "memory");
            if (c >= (unsigned)TAB_N) break;
            __nanosleep(64);
        }
    }
    __syncthreads();

    for (int i = tid; i < TAB_N; i += BLK) s_tab[i] = g_table[i];
    if (tid < 3) s_minv[tid] = minv_g[tid];
    __syncthreads();                  // table + mbar inits visible block-wide

    const float mi0 = s_minv[0], mi1 = s_minv[1], mi2 = s_minv[2];

    // ---- R15 ring: compute tile t while t+2 loads and t-1 stores ----
    for (int t = 0; t < nt; t++) {
        const int s  = t % STAGES;
        const unsigned ph = (unsigned)((t / STAGES) & 1);
        mbar_wait(mb0 + 8u * s, ph);              // tile t landed

        sample_row(sbuf[s] + tid * 18, s_tab, mi0, mi1, mi2);
        __syncthreads();                          // all rows written

        if (tid == 0) {
            asm volatile("fence.proxy.async.shared::cta;" ::: "memory");
            asm volatile(
                "cp.async.bulk.global.shared::cta.bulk_group [%0], [%1], %2;"
                :: "l"(out + (size_t)(tile0 + t) * (SPB * 18)),
                   "r"(smem_u32(sbuf[s])), "r"((unsigned)TILE_BYTES)
                : "memory");
            asm volatile("cp.async.bulk.commit_group;" ::: "memory");

            const int u = t + STAGES - 1;         // tile to prefetch
            if (u < nt) {
                if (t >= 1)   // slot u%STAGES was stored from at iter t-1
                    asm volatile("cp.async.bulk.wait_group 1;" ::: "memory");
                const unsigned mbu = mb0 + 8u * (u % STAGES);
                asm volatile("mbarrier.arrive.expect_tx.shared.b64 _, [%0], %1;"
                             :: "r"(mbu), "r"((unsigned)TILE_BYTES) : "memory");
                asm volatile(
                    "cp.async.bulk.shared::cta.global.mbarrier::complete_tx::bytes "
                    "[%0], [%1], %2, [%3];"
                    :: "r"(smem_u32(sbuf[u % STAGES])),
                       "l"(z + (size_t)(tile0 + u) * (SPB * 18)),
                       "r"((unsigned)TILE_BYTES), "r"(mbu)
                    : "memory");
            }
        }
    }
    if (tid == 0 && nt > 0)
        asm volatile("cp.async.bulk.wait_group 0;" ::: "memory");  // stores done

    // global remainder tile (B % SPB != 0): block 0, direct scalar path
    if (bid == 0 && (B % SPB) != 0) {
        const int base = ntf * SPB;
        const int rem  = B - base;
        if (tid < rem) {
            float row[18];
            const float* src = z + (size_t)(base + tid) * 18;
            #pragma unroll
            for (int c = 0; c < 18; c++) row[c] = src[c];
            sample_row(row, s_tab, mi0, mi1, mi2);
            float* dst = out + (size_t)(base + tid) * 18;
            #pragma unroll
            for (int c = 0; c < 18; c++) dst[c] = row[c];
        }
    }

    // ---- epilogue: last-finishing block resets counters (replay-safe) ----
    __syncthreads();
    if (tid == 0) {
        const unsigned old = atomicAdd(&g_fin, 1u);
        if (old == (unsigned)gridDim.x - 1u) {
            asm volatile("st.global.cg.u32 [%0], %1;"
                         :: "l"(&g_done), "r"(0u) : "memory");
            asm volatile("st.global.cg.u32 [%0], %1;"
                         :: "l"(&g_fin), "r"(0u) : "memory");
        }
    }
}

extern "C" void kernel_launch(void* const* d_in, const int* in_sizes, int n_in,
                              void* d_out, int out_size)
{
    const float* z     = (const float*)d_in[0];
    const float* log_m = (const float*)d_in[1];
    const float* W1    = (const float*)d_in[2];
    const float* b1    = (const float*)d_in[3];
    const float* W2    = (const float*)d_in[4];
    const float* b2    = (const float*)d_in[5];
    const float* W3    = (const float*)d_in[6];
    // d_in[7] = b3 drops out of the gradient
    float* out = (float*)d_out;
    const int B = in_sizes[0] / 18;

    const int ntf  = B / SPB;                            // 2048 full tiles
    int grid = max(1, (ntf + TPB - 1) / TPB);            // 512
    if (grid < TAB_N) grid = TAB_N;                      // builders must exist

    hnn_fused<<<grid, BLK>>>(z, log_m, W1, b1, W2, b2, W3, out, B);
}